// round 3
// baseline (speedup 1.0000x reference)
#include <cuda_runtime.h>
#include <math.h>

#define NN 50000
#define EE 800000
#define BG 512
#define D  128

// ---------------- scratch (static device globals; no allocation) ----------------
__device__ int   g_deg[NN];
__device__ int   g_rowptr[NN + 1];
__device__ int   g_cursor[NN];
__device__ int   g_col[EE];
__device__ int   g_root[BG + 1];
__device__ float g_mean[NN * D];
__device__ float g_h1[NN * D];
__device__ float g_h2[NN * D];
__device__ float g_pool[BG * D];
__device__ float g_f1[BG * 256];
__device__ float g_f2[BG * D];

// ---------------- packed f32x2 helpers ----------------
__device__ __forceinline__ void fma2(unsigned long long& d,
                                     unsigned long long a,
                                     unsigned long long b) {
    asm("fma.rn.f32x2 %0, %1, %2, %0;" : "+l"(d) : "l"(a), "l"(b));
}
__device__ __forceinline__ unsigned long long bcast2(float x) {
    unsigned long long r;
    asm("mov.b64 %0, {%1, %1};" : "=l"(r) : "f"(x));
    return r;
}
__device__ __forceinline__ void unpack2(unsigned long long v, float& lo, float& hi) {
    asm("mov.b64 {%0, %1}, %2;" : "=f"(lo), "=f"(hi) : "l"(v));
}

// ---------------- CSR build ----------------
__global__ void k_zero_deg() {
    int i = blockIdx.x * blockDim.x + threadIdx.x;
    if (i < NN) g_deg[i] = 0;
}

__global__ void k_hist(const int* __restrict__ dst) {
    int e = blockIdx.x * blockDim.x + threadIdx.x;
    if (e < EE) atomicAdd(&g_deg[dst[e]], 1);
}

__global__ void k_scan() {
    // single block, 1024 threads, exclusive scan of g_deg -> g_rowptr
    const int C = (NN + 1023) / 1024;  // 49
    __shared__ int part[1024];
    int t = threadIdx.x;
    int base = t * C;
    int s = 0;
    for (int q = 0; q < C; q++) {
        int i = base + q;
        if (i < NN) s += g_deg[i];
    }
    part[t] = s;
    __syncthreads();
    for (int off = 1; off < 1024; off <<= 1) {
        int add = (t >= off) ? part[t - off] : 0;
        __syncthreads();
        part[t] += add;
        __syncthreads();
    }
    int excl = (t == 0) ? 0 : part[t - 1];
    for (int q = 0; q < C; q++) {
        int i = base + q;
        if (i < NN) {
            int d = g_deg[i];
            g_rowptr[i] = excl;
            excl += d;
        }
    }
    if (t == 1023) g_rowptr[NN] = part[1023];
}

__global__ void k_copy_cursor() {
    int i = blockIdx.x * blockDim.x + threadIdx.x;
    if (i < NN) g_cursor[i] = g_rowptr[i];
}

__global__ void k_fill(const int* __restrict__ src, const int* __restrict__ dst) {
    int e = blockIdx.x * blockDim.x + threadIdx.x;
    if (e < EE) {
        int d = dst[e];
        int p = atomicAdd(&g_cursor[d], 1);
        g_col[p] = src[e];
    }
}

__global__ void k_root(const int* __restrict__ batch) {
    int i = blockIdx.x * blockDim.x + threadIdx.x;
    if (i < NN) {
        int b = batch[i];
        if (i == 0 || batch[i - 1] != b) g_root[b] = i;
        if (i == 0) g_root[BG] = NN;
    }
}

// ---------------- mean aggregation: warp per node, lane = one float4 ----------------
__global__ void k_aggregate(const float* __restrict__ feat, float* __restrict__ mean) {
    int warp = (blockIdx.x * blockDim.x + threadIdx.x) >> 5;
    int lane = threadIdx.x & 31;
    if (warp >= NN) return;
    int s = g_rowptr[warp];
    int e = g_rowptr[warp + 1];
    float4 acc = make_float4(0.f, 0.f, 0.f, 0.f);
    const float4* f4 = (const float4*)feat;
    for (int i = s; i < e; i++) {
        int c = __ldg(&g_col[i]);
        float4 v = __ldg(&f4[c * 32 + lane]);
        acc.x += v.x; acc.y += v.y; acc.z += v.z; acc.w += v.w;
    }
    int cnt = e - s;
    float inv = 1.0f / (float)(cnt > 0 ? cnt : 1);
    acc.x *= inv; acc.y *= inv; acc.z *= inv; acc.w *= inv;
    ((float4*)mean)[warp * 32 + lane] = acc;
}

// ---------------- SAGE GEMM: out = relu(mean@Wl + feat@Wr + bl) ----------------
// M-tile 128, N=128 (full), K-tile 64. 256 threads: jt(16) x nt(16).
// Each thread: 8 rows (nt + 16*i) x 8 cols (jt*8..jt*8+7) via f32x2 pairs.
__global__ __launch_bounds__(256, 2)
void k_gemm_sage(const float* __restrict__ Amean, const float* __restrict__ Afeat,
                 const float* __restrict__ Wl, const float* __restrict__ Wr,
                 const float* __restrict__ bias, float* __restrict__ out) {
    extern __shared__ float smem[];
    float* sA = smem;                        // [128][68]
    float4* sW = (float4*)(smem + 128 * 68); // [64][32] float4 = 64x128 floats

    const int tid = threadIdx.x;
    const int jt = tid & 15;
    const int nt = tid >> 4;
    const int row0 = blockIdx.x * 128;

    unsigned long long acc[8][4];
#pragma unroll
    for (int i = 0; i < 8; i++)
#pragma unroll
        for (int j = 0; j < 4; j++) acc[i][j] = 0ull;

    for (int t = 0; t < 4; t++) {
        const float* A = (t < 2) ? Amean : Afeat;
        const float* W = (t < 2) ? Wl : Wr;
        const int kb = (t & 1) * 64;

        // load W tile (64x128 floats = 2048 float4)
        {
            const float4* Wg = (const float4*)W + kb * 32;
#pragma unroll
            for (int q = 0; q < 8; q++) {
                int lin = tid + q * 256;
                sW[lin] = Wg[lin];
            }
        }
        // load A tile (128 rows x 64 k), row = tid>>1, half = tid&1
        {
            int r = tid >> 1;
            int kh = (tid & 1) * 32;
            int grow = row0 + r;
            const float4* Ag = (const float4*)(A + (size_t)grow * D + kb + kh);
            float* sdst = &sA[r * 68 + kh];
#pragma unroll
            for (int q = 0; q < 8; q++) {
                float4 v = make_float4(0.f, 0.f, 0.f, 0.f);
                if (grow < NN) v = Ag[q];
                *((float4*)(sdst + q * 4)) = v;
            }
        }
        __syncthreads();

#pragma unroll 8
        for (int k = 0; k < 64; k++) {
            ulonglong2 p0 = ((const ulonglong2*)sW)[k * 32 + jt * 2];
            ulonglong2 p1 = ((const ulonglong2*)sW)[k * 32 + jt * 2 + 1];
#pragma unroll
            for (int i = 0; i < 8; i++) {
                unsigned long long aa = bcast2(sA[(nt + 16 * i) * 68 + k]);
                fma2(acc[i][0], aa, p0.x);
                fma2(acc[i][1], aa, p0.y);
                fma2(acc[i][2], aa, p1.x);
                fma2(acc[i][3], aa, p1.y);
            }
        }
        __syncthreads();
    }

    float b[8];
#pragma unroll
    for (int c = 0; c < 8; c++) b[c] = bias[jt * 8 + c];

#pragma unroll
    for (int i = 0; i < 8; i++) {
        int row = row0 + nt + 16 * i;
        if (row < NN) {
            float lo[4], hi[4];
#pragma unroll
            for (int j = 0; j < 4; j++) {
                unpack2(acc[i][j], lo[j], hi[j]);
                lo[j] = fmaxf(lo[j] + b[j * 2], 0.f);
                hi[j] = fmaxf(hi[j] + b[j * 2 + 1], 0.f);
            }
            float4* o = (float4*)(out + (size_t)row * D + jt * 8);
            o[0] = make_float4(lo[0], hi[0], lo[1], hi[1]);
            o[1] = make_float4(lo[2], hi[2], lo[3], hi[3]);
        }
    }
}

// ---------------- max pool per graph (sorted batch -> contiguous ranges) ----------------
__global__ void k_pool(const float* __restrict__ h) {
    int b = blockIdx.x;
    int tid = threadIdx.x;  // 0..127
    int s = g_root[b];
    int e = g_root[b + 1];
    float m = -3.4e38f;
    for (int n = s; n < e; n++) m = fmaxf(m, h[(size_t)n * D + tid]);
    g_pool[b * D + tid] = m;
}

// ---------------- MLP 128->256 ----------------
__global__ void k_mlp1(const float* __restrict__ W, const float* __restrict__ b) {
    __shared__ float xr[128];
    int g = blockIdx.x;
    int tid = threadIdx.x;  // 0..255
    if (tid < 128) xr[tid] = g_pool[g * 128 + tid];
    __syncthreads();
    float s = b[tid];
#pragma unroll 16
    for (int k = 0; k < 128; k++) s += xr[k] * W[k * 256 + tid];
    g_f1[g * 256 + tid] = fmaxf(s, 0.f);
}

// ---------------- MLP 256->128 ----------------
__global__ void k_mlp2(const float* __restrict__ W, const float* __restrict__ b) {
    __shared__ float xr[256];
    int g = blockIdx.x;
    int tid = threadIdx.x;  // 0..127
    xr[tid] = g_f1[g * 256 + tid];
    xr[tid + 128] = g_f1[g * 256 + 128 + tid];
    __syncthreads();
    float s = b[tid];
#pragma unroll 16
    for (int k = 0; k < 256; k++) s += xr[k] * W[k * 128 + tid];
    g_f2[g * 128 + tid] = fmaxf(s, 0.f);
}

// ---------------- fused head: h_sm, news, concat@W_cat, sigmoid ----------------
__global__ void k_final(const float* __restrict__ x,
                        const float* __restrict__ Wsm, const float* __restrict__ bsm,
                        const float* __restrict__ Wnews, const float* __restrict__ bnews,
                        const float* __restrict__ Wcat, const float* __restrict__ bcat,
                        float* __restrict__ out) {
    int g = (blockIdx.x * blockDim.x + threadIdx.x) >> 5;
    int lane = threadIdx.x & 31;
    if (g >= BG) return;
    float4 fv = ((const float4*)(g_f2 + g * D))[lane];
    float4 xv = ((const float4*)(x + (size_t)g_root[g] * D))[lane];
    float ff[4] = {fv.x, fv.y, fv.z, fv.w};
    float xx[4] = {xv.x, xv.y, xv.z, xv.w};
    float s0 = 0.f, s1 = 0.f, n0 = 0.f, n1 = 0.f;
    int kb = lane * 4;
#pragma unroll
    for (int t = 0; t < 4; t++) {
        s0 += ff[t] * Wsm[(kb + t) * 2 + 0];
        s1 += ff[t] * Wsm[(kb + t) * 2 + 1];
        n0 += xx[t] * Wnews[(kb + t) * 2 + 0];
        n1 += xx[t] * Wnews[(kb + t) * 2 + 1];
    }
#pragma unroll
    for (int off = 16; off > 0; off >>= 1) {
        s0 += __shfl_down_sync(0xffffffffu, s0, off);
        s1 += __shfl_down_sync(0xffffffffu, s1, off);
        n0 += __shfl_down_sync(0xffffffffu, n0, off);
        n1 += __shfl_down_sync(0xffffffffu, n1, off);
    }
    if (lane == 0) {
        float h0 = fmaxf(s0 + bsm[0], 0.f);
        float h1 = fmaxf(s1 + bsm[1], 0.f);
        float m0 = fmaxf(n0 + bnews[0], 0.f);
        float m1 = fmaxf(n1 + bnews[1], 0.f);
        float z = h0 * Wcat[0] + h1 * Wcat[1] + m0 * Wcat[2] + m1 * Wcat[3] + bcat[0];
        out[g] = 1.0f / (1.0f + expf(-z));
    }
}

// ---------------- launch ----------------
extern "C" void kernel_launch(void* const* d_in, const int* in_sizes, int n_in,
                              void* d_out, int out_size) {
    const float* x     = (const float*)d_in[0];
    const int*   ei    = (const int*)d_in[1];
    const int*   src   = ei;
    const int*   dst   = ei + EE;
    const int*   batch = (const int*)d_in[2];
    const float* Wl1 = (const float*)d_in[3];
    const float* Wr1 = (const float*)d_in[4];
    const float* bl1 = (const float*)d_in[5];
    const float* Wl2 = (const float*)d_in[6];
    const float* Wr2 = (const float*)d_in[7];
    const float* bl2 = (const float*)d_in[8];
    const float* Wl3 = (const float*)d_in[9];
    const float* Wr3 = (const float*)d_in[10];
    const float* bl3 = (const float*)d_in[11];
    const float* W_f1 = (const float*)d_in[12];
    const float* b_f1 = (const float*)d_in[13];
    const float* W_f2 = (const float*)d_in[14];
    const float* b_f2 = (const float*)d_in[15];
    const float* W_sm = (const float*)d_in[16];
    const float* b_sm = (const float*)d_in[17];
    const float* W_news = (const float*)d_in[18];
    const float* b_news = (const float*)d_in[19];
    const float* W_cat = (const float*)d_in[20];
    const float* b_cat = (const float*)d_in[21];
    float* out = (float*)d_out;

    float *mean, *h1, *h2;
    cudaGetSymbolAddress((void**)&mean, g_mean);
    cudaGetSymbolAddress((void**)&h1, g_h1);
    cudaGetSymbolAddress((void**)&h2, g_h2);

    const int TB = 256;
    const int gN = (NN + TB - 1) / TB;
    const int gE = (EE + TB - 1) / TB;

    // CSR build (reused by all 3 layers) + per-graph roots
    k_zero_deg<<<gN, TB>>>();
    k_hist<<<gE, TB>>>(dst);
    k_scan<<<1, 1024>>>();
    k_copy_cursor<<<gN, TB>>>();
    k_fill<<<gE, TB>>>(src, dst);
    k_root<<<gN, TB>>>(batch);

    const int gAgg = (NN * 32 + TB - 1) / TB;  // warp per node
    const int gGemm = (NN + 127) / 128;
    size_t shbytes = (size_t)(128 * 68 + 64 * 128) * sizeof(float);
    cudaFuncSetAttribute(k_gemm_sage, cudaFuncAttributeMaxDynamicSharedMemorySize,
                         (int)shbytes);

    // layer 1: x -> h1
    k_aggregate<<<gAgg, TB>>>(x, mean);
    k_gemm_sage<<<gGemm, TB, shbytes>>>(mean, x, Wl1, Wr1, bl1, h1);
    // layer 2: h1 -> h2
    k_aggregate<<<gAgg, TB>>>(h1, mean);
    k_gemm_sage<<<gGemm, TB, shbytes>>>(mean, h1, Wl2, Wr2, bl2, h2);
    // layer 3: h2 -> h1
    k_aggregate<<<gAgg, TB>>>(h2, mean);
    k_gemm_sage<<<gGemm, TB, shbytes>>>(mean, h2, Wl3, Wr3, bl3, h1);

    // pooled head
    k_pool<<<BG, 128>>>(h1);
    k_mlp1<<<BG, 256>>>(W_f1, b_f1);
    k_mlp2<<<BG, 128>>>(W_f2, b_f2);
    k_final<<<(BG * 32 + TB - 1) / TB, TB>>>(x, W_sm, b_sm, W_news, b_news,
                                             W_cat, b_cat, out);
}